// round 2
// baseline (speedup 1.0000x reference)
#include <cuda_runtime.h>

// ---------------------------------------------------------------------------
// ChunkedLocalAttention (landmark attention), fp32 baseline
// B=2, S=8192, D=768, H=12, hd=64, CHUNK=512, N_LM=32
// ---------------------------------------------------------------------------

#define NB   2
#define SQL  8192
#define DM   768
#define NH   12
#define HD   64
#define CK   512
#define NLM  32
#define NCH  16            // SQL / CK
#define KVL  544           // NLM + CK
#define SEG  256           // SQL / NLM
#define SPAD 548           // padded score row stride (multiple of 4)

// ---- device scratch (no allocations allowed) ------------------------------
__device__ float g_lm [NB*NLM*DM];
__device__ float g_klm[NB*NLM*DM];
__device__ float g_vlm[NB*NLM*DM];
__device__ float g_q  [NB*SQL*DM];
__device__ float g_kx [NB*SQL*DM];
__device__ float g_vx [NB*SQL*DM];
__device__ float g_ao [NB*SQL*DM];

// ---------------------------------------------------------------------------
// Landmark mean-pool: lm[b,l,:] = mean over SEG tokens of x
// grid = NB*NLM blocks, 256 threads (each owns 3 of 768 dims)
// ---------------------------------------------------------------------------
__global__ __launch_bounds__(256) void lm_kernel(const float* __restrict__ x)
{
    const int b = blockIdx.x / NLM;
    const int l = blockIdx.x % NLM;
    const float* xp = x + ((size_t)(b * SQL) + (size_t)l * SEG) * DM;
    const int t = threadIdx.x;
    float a0 = 0.f, a1 = 0.f, a2 = 0.f;
    for (int s = 0; s < SEG; s++) {
        const float* r = xp + (size_t)s * DM;
        a0 += r[t];
        a1 += r[t + 256];
        a2 += r[t + 512];
    }
    float* o = g_lm + (size_t)(b * NLM + l) * DM;
    const float inv = 1.0f / (float)SEG;
    o[t]       = a0 * inv;
    o[t + 256] = a1 * inv;
    o[t + 512] = a2 * inv;
}

// ---------------------------------------------------------------------------
// SGEMM:  C[M,N] = A[M,K] * W[N,K]^T + bias[N]
// 128x128 block tile, BK=16, 256 threads, 8x8 microtile,
// register-prefetch pipeline on the global loads.
// ---------------------------------------------------------------------------
__global__ __launch_bounds__(256, 2) void sgemm_abt(
    const float* __restrict__ A, const float* __restrict__ W,
    const float* __restrict__ bias, float* __restrict__ C,
    int M, int N, int K)
{
    __shared__ float As[16][132];   // [k][m], padded
    __shared__ float Bs[16][132];   // [k][n], padded

    const int tid = threadIdx.x;
    const int tx  = tid & 15;       // column group (8 cols)
    const int ty  = tid >> 4;       // row group (8 rows)
    const int rowBlk = blockIdx.y * 128;
    const int colBlk = blockIdx.x * 128;
    const int lr = tid >> 2;        // 0..63
    const int lk = (tid & 3) << 2;  // 0,4,8,12

    float acc[8][8];
#pragma unroll
    for (int i = 0; i < 8; i++)
#pragma unroll
        for (int j = 0; j < 8; j++) acc[i][j] = 0.f;

    // prefetch slab 0 into registers
    float4 pa[2], pb[2];
#pragma unroll
    for (int rr = 0; rr < 2; rr++) {
        const int r  = lr + rr * 64;
        const int ga = rowBlk + r;
        pa[rr] = make_float4(0.f, 0.f, 0.f, 0.f);
        if (ga < M) pa[rr] = *(const float4*)&A[(size_t)ga * K + lk];
        pb[rr] = *(const float4*)&W[(size_t)(colBlk + r) * K + lk];
    }

    for (int kt = 0; kt < K; kt += 16) {
        // stage registers -> smem
#pragma unroll
        for (int rr = 0; rr < 2; rr++) {
            const int r = lr + rr * 64;
            As[lk + 0][r] = pa[rr].x; As[lk + 1][r] = pa[rr].y;
            As[lk + 2][r] = pa[rr].z; As[lk + 3][r] = pa[rr].w;
            Bs[lk + 0][r] = pb[rr].x; Bs[lk + 1][r] = pb[rr].y;
            Bs[lk + 2][r] = pb[rr].z; Bs[lk + 3][r] = pb[rr].w;
        }
        __syncthreads();

        // prefetch next slab while computing this one
        const int ktn = kt + 16;
        if (ktn < K) {
#pragma unroll
            for (int rr = 0; rr < 2; rr++) {
                const int r  = lr + rr * 64;
                const int ga = rowBlk + r;
                pa[rr] = make_float4(0.f, 0.f, 0.f, 0.f);
                if (ga < M) pa[rr] = *(const float4*)&A[(size_t)ga * K + ktn + lk];
                pb[rr] = *(const float4*)&W[(size_t)(colBlk + r) * K + ktn + lk];
            }
        }

#pragma unroll
        for (int kk = 0; kk < 16; kk++) {
            float a[8], bb[8];
            *(float4*)&a[0]  = *(const float4*)&As[kk][ty * 8];
            *(float4*)&a[4]  = *(const float4*)&As[kk][ty * 8 + 4];
            *(float4*)&bb[0] = *(const float4*)&Bs[kk][tx * 8];
            *(float4*)&bb[4] = *(const float4*)&Bs[kk][tx * 8 + 4];
#pragma unroll
            for (int i = 0; i < 8; i++)
#pragma unroll
                for (int j = 0; j < 8; j++)
                    acc[i][j] += a[i] * bb[j];
        }
        __syncthreads();
    }

#pragma unroll
    for (int i = 0; i < 8; i++) {
        const int gr = rowBlk + ty * 8 + i;
        if (gr < M) {
#pragma unroll
            for (int j = 0; j < 8; j += 4) {
                const int gc = colBlk + tx * 8 + j;
                float4 v;
                v.x = acc[i][j + 0] + bias[gc + 0];
                v.y = acc[i][j + 1] + bias[gc + 1];
                v.z = acc[i][j + 2] + bias[gc + 2];
                v.w = acc[i][j + 3] + bias[gc + 3];
                *(float4*)&C[(size_t)gr * N + gc] = v;
            }
        }
    }
}

// ---------------------------------------------------------------------------
// Fused attention: per block = (qtile of 64 rows, head, b*chunk)
// Phase 1: S = scale * Q(64x64) K(544x64)^T   -> smem scores [64][SPAD]
// Phase 2: row softmax over 544 (8 warps x 8 rows)
// Phase 3: O(64x64) = P(64x544) V(544x64)     -> g_ao
// K/V rows j<32 come from landmark K/V, else from token K/V of this chunk.
// ---------------------------------------------------------------------------
#define ATTN_SMEM_FLOATS (64 * 64 + 32 * 64 + 64 * SPAD)

__global__ __launch_bounds__(256) void attn_kernel()
{
    extern __shared__ float sm[];
    float* sQ  = sm;                 // [d][q] : 64*64
    float* sKV = sm + 64 * 64;       // 32*64 (tile of K^T or V)
    float* sS  = sKV + 32 * 64;      // [q][SPAD]

    const int tid = threadIdx.x;
    const int qt  = blockIdx.x;      // 0..7
    const int h   = blockIdx.y;      // 0..11
    const int bc  = blockIdx.z;      // 0..31
    const int b   = bc >> 4;
    const int c   = bc & 15;
    const float scale = 0.125f;      // hd^-0.5

    const size_t tokBase = (size_t)(b * SQL + c * CK);

    // ---- load Q tile (transposed: sQ[d*64+q]) ----
    {
        const int q  = tid >> 2;
        const int dg = (tid & 3) * 16;
        const float* qr = g_q + (tokBase + qt * 64 + q) * DM + h * HD;
#pragma unroll
        for (int i = 0; i < 4; i++) {
            const float4 v = *(const float4*)&qr[dg + i * 4];
            sQ[(dg + i * 4 + 0) * 64 + q] = v.x;
            sQ[(dg + i * 4 + 1) * 64 + q] = v.y;
            sQ[(dg + i * 4 + 2) * 64 + q] = v.z;
            sQ[(dg + i * 4 + 3) * 64 + q] = v.w;
        }
    }

    const int ty = tid >> 4;   // 0..15 -> 4 q rows
    const int tx = tid & 15;   // 0..15 -> 2 keys (phase1) / 4 dims (phase3)

    // ---- Phase 1: scores ----
    for (int kt = 0; kt < 17; kt++) {
        __syncthreads();   // protect sKV reuse (and sQ writes on kt==0)
        {
            const int j  = tid >> 3;          // 0..31
            const int dg = (tid & 7) * 8;
            const int gj = kt * 32 + j;
            const float* kr = (gj < NLM)
                ? g_klm + ((size_t)(b * NLM + gj)) * DM + h * HD
                : g_kx  + (tokBase + (gj - NLM)) * DM + h * HD;
#pragma unroll
            for (int i = 0; i < 2; i++) {
                const float4 v = *(const float4*)&kr[dg + i * 4];
                sKV[(dg + i * 4 + 0) * 32 + j] = v.x;
                sKV[(dg + i * 4 + 1) * 32 + j] = v.y;
                sKV[(dg + i * 4 + 2) * 32 + j] = v.z;
                sKV[(dg + i * 4 + 3) * 32 + j] = v.w;
            }
        }
        __syncthreads();

        float acc[4][2] = {{0.f,0.f},{0.f,0.f},{0.f,0.f},{0.f,0.f}};
#pragma unroll 8
        for (int d = 0; d < 64; d++) {
            const float4 a  = *(const float4*)&sQ[d * 64 + ty * 4];
            const float2 bb = *(const float2*)&sKV[d * 32 + tx * 2];
            acc[0][0] += a.x * bb.x; acc[0][1] += a.x * bb.y;
            acc[1][0] += a.y * bb.x; acc[1][1] += a.y * bb.y;
            acc[2][0] += a.z * bb.x; acc[2][1] += a.z * bb.y;
            acc[3][0] += a.w * bb.x; acc[3][1] += a.w * bb.y;
        }
#pragma unroll
        for (int i = 0; i < 4; i++) {
            sS[(ty * 4 + i) * SPAD + kt * 32 + tx * 2 + 0] = acc[i][0] * scale;
            sS[(ty * 4 + i) * SPAD + kt * 32 + tx * 2 + 1] = acc[i][1] * scale;
        }
    }
    __syncthreads();

    // ---- Phase 2: softmax ----
    {
        const int w    = tid >> 5;
        const int lane = tid & 31;
        for (int rr = 0; rr < 8; rr++) {
            float* row = sS + (size_t)(w * 8 + rr) * SPAD;
            float m = -1e30f;
            for (int j = lane; j < KVL; j += 32) m = fmaxf(m, row[j]);
#pragma unroll
            for (int o = 16; o > 0; o >>= 1) m = fmaxf(m, __shfl_xor_sync(0xffffffffu, m, o));
            float ssum = 0.f;
            for (int j = lane; j < KVL; j += 32) {
                const float e = __expf(row[j] - m);
                row[j] = e;
                ssum += e;
            }
#pragma unroll
            for (int o = 16; o > 0; o >>= 1) ssum += __shfl_xor_sync(0xffffffffu, ssum, o);
            const float inv = 1.0f / ssum;
            for (int j = lane; j < KVL; j += 32) row[j] *= inv;
        }
    }

    // ---- Phase 3: O = P * V ----
    float oc[4][4] = {{0.f,0.f,0.f,0.f},{0.f,0.f,0.f,0.f},
                      {0.f,0.f,0.f,0.f},{0.f,0.f,0.f,0.f}};
    for (int kt = 0; kt < 17; kt++) {
        __syncthreads();   // all threads past softmax / previous compute
        {
            const int j  = tid >> 3;
            const int dg = (tid & 7) * 8;
            const int gj = kt * 32 + j;
            const float* vr = (gj < NLM)
                ? g_vlm + ((size_t)(b * NLM + gj)) * DM + h * HD
                : g_vx  + (tokBase + (gj - NLM)) * DM + h * HD;
            *(float4*)&sKV[j * 64 + dg]     = *(const float4*)&vr[dg];
            *(float4*)&sKV[j * 64 + dg + 4] = *(const float4*)&vr[dg + 4];
        }
        __syncthreads();

#pragma unroll 4
        for (int jj = 0; jj < 32; jj++) {
            const float p0 = sS[(ty * 4 + 0) * SPAD + kt * 32 + jj];
            const float p1 = sS[(ty * 4 + 1) * SPAD + kt * 32 + jj];
            const float p2 = sS[(ty * 4 + 2) * SPAD + kt * 32 + jj];
            const float p3 = sS[(ty * 4 + 3) * SPAD + kt * 32 + jj];
            const float4 v = *(const float4*)&sKV[jj * 64 + tx * 4];
            oc[0][0] += p0 * v.x; oc[0][1] += p0 * v.y; oc[0][2] += p0 * v.z; oc[0][3] += p0 * v.w;
            oc[1][0] += p1 * v.x; oc[1][1] += p1 * v.y; oc[1][2] += p1 * v.z; oc[1][3] += p1 * v.w;
            oc[2][0] += p2 * v.x; oc[2][1] += p2 * v.y; oc[2][2] += p2 * v.z; oc[2][3] += p2 * v.w;
            oc[3][0] += p3 * v.x; oc[3][1] += p3 * v.y; oc[3][2] += p3 * v.z; oc[3][3] += p3 * v.w;
        }
    }

    // ---- store attention output ----
    {
        const size_t base = (tokBase + qt * 64 + ty * 4) * DM + h * HD + tx * 4;
#pragma unroll
        for (int i = 0; i < 4; i++) {
            const float4 v = make_float4(oc[i][0], oc[i][1], oc[i][2], oc[i][3]);
            *(float4*)&g_ao[base + (size_t)i * DM] = v;
        }
    }
}

// ---------------------------------------------------------------------------
// Launch
// ---------------------------------------------------------------------------
extern "C" void kernel_launch(void* const* d_in, const int* in_sizes, int n_in,
                              void* d_out, int out_size)
{
    (void)in_sizes; (void)n_in; (void)out_size;
    const float* x  = (const float*)d_in[0];
    const float* Wq = (const float*)d_in[1];
    const float* bq = (const float*)d_in[2];
    const float* Wk = (const float*)d_in[3];
    const float* bk = (const float*)d_in[4];
    const float* Wv = (const float*)d_in[5];
    const float* bv = (const float*)d_in[6];
    const float* Wo = (const float*)d_in[7];
    const float* bo = (const float*)d_in[8];
    float* out = (float*)d_out;

    float *p_lm, *p_klm, *p_vlm, *p_q, *p_kx, *p_vx, *p_ao;
    cudaGetSymbolAddress((void**)&p_lm,  g_lm);
    cudaGetSymbolAddress((void**)&p_klm, g_klm);
    cudaGetSymbolAddress((void**)&p_vlm, g_vlm);
    cudaGetSymbolAddress((void**)&p_q,   g_q);
    cudaGetSymbolAddress((void**)&p_kx,  g_kx);
    cudaGetSymbolAddress((void**)&p_vx,  g_vx);
    cudaGetSymbolAddress((void**)&p_ao,  g_ao);

    const int attn_smem = ATTN_SMEM_FLOATS * (int)sizeof(float);
    cudaFuncSetAttribute(attn_kernel,
                         cudaFuncAttributeMaxDynamicSharedMemorySize, attn_smem);

    // 1) landmarks
    lm_kernel<<<NB * NLM, 256>>>(x);

    // 2) projections
    const dim3 gproj(DM / 128, (NB * SQL) / 128);
    sgemm_abt<<<gproj, 256>>>(x, Wq, bq, p_q,  NB * SQL, DM, DM);
    sgemm_abt<<<gproj, 256>>>(x, Wk, bk, p_kx, NB * SQL, DM, DM);
    sgemm_abt<<<gproj, 256>>>(x, Wv, bv, p_vx, NB * SQL, DM, DM);
    const dim3 glm(DM / 128, 1);
    sgemm_abt<<<glm, 256>>>(p_lm, Wk, bk, p_klm, NB * NLM, DM, DM);
    sgemm_abt<<<glm, 256>>>(p_lm, Wv, bv, p_vlm, NB * NLM, DM, DM);

    // 3) fused chunked attention
    attn_kernel<<<dim3(CK / 64, NH, NB * NCH), 256, attn_smem>>>();

    // 4) output projection
    sgemm_abt<<<gproj, 256>>>(p_ao, Wo, bo, out, NB * SQL, DM, DM);
}

// round 6
// speedup vs baseline: 1.3357x; 1.3357x over previous
#include <cuda_runtime.h>
#include <cuda_bf16.h>
#include <cstdint>

// ---------------------------------------------------------------------------
// ChunkedLocalAttention: mma.sync split-bf16 GEMMs + fp32 fused attention
// B=2, S=8192, D=768, H=12, hd=64, CHUNK=512, N_LM=32
// NOTE: harness compiles for plain sm_100 (no 'a') -> tcgen05 unavailable.
//       Use stable-ISA ldmatrix + mma.sync (HMMA) instead.
// ---------------------------------------------------------------------------

#define NB   2
#define SQL  8192
#define DM   768
#define NH   12
#define HD   64
#define CK   512
#define NLM  32
#define NCH  16
#define KVL  544
#define SEG  256
#define SPAD 548

// ---- device scratch -------------------------------------------------------
__device__ float g_lm [NB*NLM*DM];
__device__ float g_klm[NB*NLM*DM];
__device__ float g_vlm[NB*NLM*DM];
__device__ float g_q  [NB*SQL*DM];
__device__ float g_kx [NB*SQL*DM];
__device__ float g_vx [NB*SQL*DM];
__device__ float g_ao [NB*SQL*DM];

// ===========================================================================
// warp-mma helpers (stable ISA: sm_80+)
// ===========================================================================
__device__ __forceinline__ uint32_t smem_u32(const void* p) {
    return (uint32_t)__cvta_generic_to_shared(p);
}
__device__ __forceinline__ void ldsm_x4(uint32_t addr, uint32_t* r) {
    asm volatile("ldmatrix.sync.aligned.m8n8.x4.shared.b16 {%0,%1,%2,%3}, [%4];"
                 : "=r"(r[0]), "=r"(r[1]), "=r"(r[2]), "=r"(r[3]) : "r"(addr));
}
__device__ __forceinline__ void ldsm_x2(uint32_t addr, uint32_t* r) {
    asm volatile("ldmatrix.sync.aligned.m8n8.x2.shared.b16 {%0,%1}, [%2];"
                 : "=r"(r[0]), "=r"(r[1]) : "r"(addr));
}
__device__ __forceinline__ void mma16816(float* c, const uint32_t* a, const uint32_t* b) {
    asm volatile("mma.sync.aligned.m16n8k16.row.col.f32.bf16.bf16.f32 "
                 "{%0,%1,%2,%3}, {%4,%5,%6,%7}, {%8,%9}, {%0,%1,%2,%3};"
                 : "+f"(c[0]), "+f"(c[1]), "+f"(c[2]), "+f"(c[3])
                 : "r"(a[0]), "r"(a[1]), "r"(a[2]), "r"(a[3]), "r"(b[0]), "r"(b[1]));
}

// split 8 fp32 -> hi/lo bf16 packs ;  x = hi + lo with |lo| <= 2^-9 |x|
__device__ __forceinline__ void cvt8(float4 a, float4 b, uint4& hi, uint4& lo) {
    float v[8] = {a.x, a.y, a.z, a.w, b.x, b.y, b.z, b.w};
    uint32_t h[8], l[8];
#pragma unroll
    for (int i = 0; i < 8; i++) {
        __nv_bfloat16 bh = __float2bfloat16(v[i]);
        __nv_bfloat16 bl = __float2bfloat16(v[i] - __bfloat162float(bh));
        h[i] = (uint32_t)__bfloat16_as_ushort(bh);
        l[i] = (uint32_t)__bfloat16_as_ushort(bl);
    }
    hi = make_uint4(h[0] | (h[1] << 16), h[2] | (h[3] << 16),
                    h[4] | (h[5] << 16), h[6] | (h[7] << 16));
    lo = make_uint4(l[0] | (l[1] << 16), l[2] | (l[3] << 16),
                    l[4] | (l[5] << 16), l[6] | (l[7] << 16));
}

// ===========================================================================
// mma.sync GEMM: C[M,768] = A[M,768] * W[768,768]^T + bias ; M % 128 == 0
// CTA 128x128, BK=32, 8 warps (2M x 4N), warp tile 64x32, split-bf16 3-pass:
//   C += Ah*Bh + Ah*Bl + Al*Bh   (Al*Bl term ~2^-18, dropped)
// ===========================================================================
#define LDSR 40    // smem row stride in bf16 elems (80B, conflict-free ldmatrix)

__global__ __launch_bounds__(256, 1) void mma_gemm(
    const float* __restrict__ A, const float* __restrict__ W,
    const float* __restrict__ bias, float* __restrict__ C)
{
    __shared__ __align__(16) __nv_bfloat16 sAh[128 * LDSR];
    __shared__ __align__(16) __nv_bfloat16 sAl[128 * LDSR];
    __shared__ __align__(16) __nv_bfloat16 sBh[128 * LDSR];
    __shared__ __align__(16) __nv_bfloat16 sBl[128 * LDSR];
    __shared__ float sBias[128];

    const int tid  = threadIdx.x;
    const int wid  = tid >> 5;
    const int lane = tid & 31;
    const int wm   = wid & 1;        // 0..1 -> 64 rows
    const int wn   = wid >> 1;       // 0..3 -> 32 cols
    const int rowBlk = blockIdx.y * 128;
    const int colBlk = blockIdx.x * 128;

    if (tid < 128) sBias[tid] = bias[colBlk + tid];

    // per-thread global staging: row = tid>>1, colSeg = (tid&1)*16
    const int ldRow = tid >> 1;
    const int ldSeg = (tid & 1) * 16;
    const float* gA = A + (size_t)(rowBlk + ldRow) * DM + ldSeg;
    const float* gB = W + (size_t)(colBlk + ldRow) * DM + ldSeg;

    // ldmatrix base addresses (A: 16x16 x4 frag; B: 8x16 x2 frag)
    const uint32_t aOffB = (uint32_t)(((wm * 64 + (lane & 15)) * LDSR + ((lane >> 4) & 1) * 8) * 2);
    const uint32_t bOffB = (uint32_t)(((wn * 32 + (lane & 7))  * LDSR + ((lane >> 3) & 1) * 8) * 2);
    const uint32_t bAh = smem_u32(sAh) + aOffB;
    const uint32_t bAl = smem_u32(sAl) + aOffB;
    const uint32_t bBh = smem_u32(sBh) + bOffB;
    const uint32_t bBl = smem_u32(sBl) + bOffB;

    float acc[4][4][4];
#pragma unroll
    for (int i = 0; i < 4; i++)
#pragma unroll
        for (int j = 0; j < 4; j++)
#pragma unroll
            for (int k = 0; k < 4; k++) acc[i][j][k] = 0.f;

    // prefetch stage 0 into registers
    float4 pa[4], pb[4];
#pragma unroll
    for (int i = 0; i < 4; i++) {
        pa[i] = *(const float4*)(gA + i * 4);
        pb[i] = *(const float4*)(gB + i * 4);
    }

    for (int t = 0; t < DM / 32; t++) {
        // stage: convert + store to smem (loop-end sync covers WAR hazard)
        {
            uint4 hi, lo;
            const int so = ldRow * LDSR + ldSeg;
            cvt8(pa[0], pa[1], hi, lo);
            *(uint4*)&sAh[so] = hi;      *(uint4*)&sAl[so] = lo;
            cvt8(pa[2], pa[3], hi, lo);
            *(uint4*)&sAh[so + 8] = hi;  *(uint4*)&sAl[so + 8] = lo;
            cvt8(pb[0], pb[1], hi, lo);
            *(uint4*)&sBh[so] = hi;      *(uint4*)&sBl[so] = lo;
            cvt8(pb[2], pb[3], hi, lo);
            *(uint4*)&sBh[so + 8] = hi;  *(uint4*)&sBl[so + 8] = lo;
        }
        __syncthreads();

        // prefetch next stage (overlaps with mma below)
        if (t + 1 < DM / 32) {
            const int kn = (t + 1) * 32;
#pragma unroll
            for (int i = 0; i < 4; i++) {
                pa[i] = *(const float4*)(gA + kn + i * 4);
                pb[i] = *(const float4*)(gB + kn + i * 4);
            }
        }

#pragma unroll
        for (int ks = 0; ks < 2; ks++) {
            uint32_t ah[4][4], al[4][4], bh[4][2], bl[4][2];
#pragma unroll
            for (int mf = 0; mf < 4; mf++) {
                ldsm_x4(bAh + mf * (16 * LDSR * 2) + ks * 32, ah[mf]);
                ldsm_x4(bAl + mf * (16 * LDSR * 2) + ks * 32, al[mf]);
            }
#pragma unroll
            for (int nf = 0; nf < 4; nf++) {
                ldsm_x2(bBh + nf * (8 * LDSR * 2) + ks * 32, bh[nf]);
                ldsm_x2(bBl + nf * (8 * LDSR * 2) + ks * 32, bl[nf]);
            }
#pragma unroll
            for (int mf = 0; mf < 4; mf++)
#pragma unroll
                for (int nf = 0; nf < 4; nf++) {
                    mma16816(acc[mf][nf], ah[mf], bh[nf]);
                    mma16816(acc[mf][nf], ah[mf], bl[nf]);
                    mma16816(acc[mf][nf], al[mf], bh[nf]);
                }
        }
        __syncthreads();
    }

    // epilogue: acc -> C (+bias)
    const int mrow  = rowBlk + wm * 64 + (lane >> 2);
    const int cloc0 = wn * 32 + (lane & 3) * 2;
#pragma unroll
    for (int mf = 0; mf < 4; mf++) {
#pragma unroll
        for (int nf = 0; nf < 4; nf++) {
            const int cl = cloc0 + nf * 8;
            const int gc = colBlk + cl;
            float* c0 = C + (size_t)(mrow + mf * 16) * DM + gc;
            float* c1 = C + (size_t)(mrow + mf * 16 + 8) * DM + gc;
            *(float2*)c0 = make_float2(acc[mf][nf][0] + sBias[cl],
                                       acc[mf][nf][1] + sBias[cl + 1]);
            *(float2*)c1 = make_float2(acc[mf][nf][2] + sBias[cl],
                                       acc[mf][nf][3] + sBias[cl + 1]);
        }
    }
}

// ===========================================================================
// Landmark mean-pool
// ===========================================================================
__global__ __launch_bounds__(256) void lm_kernel(const float* __restrict__ x)
{
    const int b = blockIdx.x / NLM;
    const int l = blockIdx.x % NLM;
    const float* xp = x + ((size_t)(b * SQL) + (size_t)l * SEG) * DM;
    const int t = threadIdx.x;
    float a0 = 0.f, a1 = 0.f, a2 = 0.f;
    for (int s = 0; s < SEG; s++) {
        const float* r = xp + (size_t)s * DM;
        a0 += r[t]; a1 += r[t + 256]; a2 += r[t + 512];
    }
    float* o = g_lm + (size_t)(b * NLM + l) * DM;
    const float inv = 1.0f / (float)SEG;
    o[t] = a0 * inv; o[t + 256] = a1 * inv; o[t + 512] = a2 * inv;
}

// ===========================================================================
// small SIMT SGEMM for landmark K/V projections (M=64)
// ===========================================================================
__global__ __launch_bounds__(256, 2) void sgemm_abt(
    const float* __restrict__ A, const float* __restrict__ W,
    const float* __restrict__ bias, float* __restrict__ C,
    int M, int N, int K)
{
    __shared__ float As[16][132];
    __shared__ float Bs[16][132];
    const int tid = threadIdx.x;
    const int tx  = tid & 15;
    const int ty  = tid >> 4;
    const int rowBlk = blockIdx.y * 128;
    const int colBlk = blockIdx.x * 128;
    const int lr = tid >> 2;
    const int lk = (tid & 3) << 2;

    float acc[8][8];
#pragma unroll
    for (int i = 0; i < 8; i++)
#pragma unroll
        for (int j = 0; j < 8; j++) acc[i][j] = 0.f;

    for (int kt = 0; kt < K; kt += 16) {
#pragma unroll
        for (int rr = 0; rr < 2; rr++) {
            const int r = lr + rr * 64;
            const int ga = rowBlk + r;
            float4 va = make_float4(0.f, 0.f, 0.f, 0.f);
            if (ga < M) va = *(const float4*)&A[(size_t)ga * K + kt + lk];
            As[lk + 0][r] = va.x; As[lk + 1][r] = va.y;
            As[lk + 2][r] = va.z; As[lk + 3][r] = va.w;
            const float4 vb = *(const float4*)&W[(size_t)(colBlk + r) * K + kt + lk];
            Bs[lk + 0][r] = vb.x; Bs[lk + 1][r] = vb.y;
            Bs[lk + 2][r] = vb.z; Bs[lk + 3][r] = vb.w;
        }
        __syncthreads();
#pragma unroll
        for (int kk = 0; kk < 16; kk++) {
            float a[8], bb[8];
            *(float4*)&a[0]  = *(const float4*)&As[kk][ty * 8];
            *(float4*)&a[4]  = *(const float4*)&As[kk][ty * 8 + 4];
            *(float4*)&bb[0] = *(const float4*)&Bs[kk][tx * 8];
            *(float4*)&bb[4] = *(const float4*)&Bs[kk][tx * 8 + 4];
#pragma unroll
            for (int i = 0; i < 8; i++)
#pragma unroll
                for (int j = 0; j < 8; j++) acc[i][j] += a[i] * bb[j];
        }
        __syncthreads();
    }
#pragma unroll
    for (int i = 0; i < 8; i++) {
        const int gr = rowBlk + ty * 8 + i;
        if (gr < M) {
#pragma unroll
            for (int j = 0; j < 8; j += 4) {
                const int gc = colBlk + tx * 8 + j;
                float4 v;
                v.x = acc[i][j + 0] + bias[gc + 0];
                v.y = acc[i][j + 1] + bias[gc + 1];
                v.z = acc[i][j + 2] + bias[gc + 2];
                v.w = acc[i][j + 3] + bias[gc + 3];
                *(float4*)&C[(size_t)gr * N + gc] = v;
            }
        }
    }
}

// ===========================================================================
// Fused attention (fp32 SIMT, smem-resident scores)  [unchanged, passing]
// ===========================================================================
#define ATTN_SMEM_FLOATS (64 * 64 + 32 * 64 + 64 * SPAD)

__global__ __launch_bounds__(256) void attn_kernel()
{
    extern __shared__ float smf[];
    float* sQ  = smf;
    float* sKV = smf + 64 * 64;
    float* sS  = sKV + 32 * 64;

    const int tid = threadIdx.x;
    const int qt  = blockIdx.x;
    const int h   = blockIdx.y;
    const int bc  = blockIdx.z;
    const int b   = bc >> 4;
    const int c   = bc & 15;
    const float scale = 0.125f;
    const size_t tokBase = (size_t)(b * SQL + c * CK);

    {
        const int q  = tid >> 2;
        const int dg = (tid & 3) * 16;
        const float* qr = g_q + (tokBase + qt * 64 + q) * DM + h * HD;
#pragma unroll
        for (int i = 0; i < 4; i++) {
            const float4 v = *(const float4*)&qr[dg + i * 4];
            sQ[(dg + i * 4 + 0) * 64 + q] = v.x;
            sQ[(dg + i * 4 + 1) * 64 + q] = v.y;
            sQ[(dg + i * 4 + 2) * 64 + q] = v.z;
            sQ[(dg + i * 4 + 3) * 64 + q] = v.w;
        }
    }

    const int ty = tid >> 4;
    const int tx = tid & 15;

    for (int kt = 0; kt < 17; kt++) {
        __syncthreads();
        {
            const int j  = tid >> 3;
            const int dg = (tid & 7) * 8;
            const int gj = kt * 32 + j;
            const float* kr = (gj < NLM)
                ? g_klm + ((size_t)(b * NLM + gj)) * DM + h * HD
                : g_kx  + (tokBase + (gj - NLM)) * DM + h * HD;
#pragma unroll
            for (int i = 0; i < 2; i++) {
                const float4 v = *(const float4*)&kr[dg + i * 4];
                sKV[(dg + i * 4 + 0) * 32 + j] = v.x;
                sKV[(dg + i * 4 + 1) * 32 + j] = v.y;
                sKV[(dg + i * 4 + 2) * 32 + j] = v.z;
                sKV[(dg + i * 4 + 3) * 32 + j] = v.w;
            }
        }
        __syncthreads();

        float acc[4][2] = {{0.f,0.f},{0.f,0.f},{0.f,0.f},{0.f,0.f}};
#pragma unroll 8
        for (int d = 0; d < 64; d++) {
            const float4 a  = *(const float4*)&sQ[d * 64 + ty * 4];
            const float2 bb = *(const float2*)&sKV[d * 32 + tx * 2];
            acc[0][0] += a.x * bb.x; acc[0][1] += a.x * bb.y;
            acc[1][0] += a.y * bb.x; acc[1][1] += a.y * bb.y;
            acc[2][0] += a.z * bb.x; acc[2][1] += a.z * bb.y;
            acc[3][0] += a.w * bb.x; acc[3][1] += a.w * bb.y;
        }
#pragma unroll
        for (int i = 0; i < 4; i++) {
            sS[(ty * 4 + i) * SPAD + kt * 32 + tx * 2 + 0] = acc[i][0] * scale;
            sS[(ty * 4 + i) * SPAD + kt * 32 + tx * 2 + 1] = acc[i][1] * scale;
        }
    }
    __syncthreads();

    {
        const int w    = tid >> 5;
        const int lane = tid & 31;
        for (int rr = 0; rr < 8; rr++) {
            float* row = sS + (size_t)(w * 8 + rr) * SPAD;
            float m = -1e30f;
            for (int j = lane; j < KVL; j += 32) m = fmaxf(m, row[j]);
#pragma unroll
            for (int o = 16; o > 0; o >>= 1) m = fmaxf(m, __shfl_xor_sync(0xffffffffu, m, o));
            float ssum = 0.f;
            for (int j = lane; j < KVL; j += 32) {
                const float e = __expf(row[j] - m);
                row[j] = e;
                ssum += e;
            }
#pragma unroll
            for (int o = 16; o > 0; o >>= 1) ssum += __shfl_xor_sync(0xffffffffu, ssum, o);
            const float inv = 1.0f / ssum;
            for (int j = lane; j < KVL; j += 32) row[j] *= inv;
        }
    }

    float oc[4][4] = {{0.f,0.f,0.f,0.f},{0.f,0.f,0.f,0.f},
                      {0.f,0.f,0.f,0.f},{0.f,0.f,0.f,0.f}};
    for (int kt = 0; kt < 17; kt++) {
        __syncthreads();
        {
            const int j  = tid >> 3;
            const int dg = (tid & 7) * 8;
            const int gj = kt * 32 + j;
            const float* vr = (gj < NLM)
                ? g_vlm + ((size_t)(b * NLM + gj)) * DM + h * HD
                : g_vx  + (tokBase + (gj - NLM)) * DM + h * HD;
            *(float4*)&sKV[j * 64 + dg]     = *(const float4*)&vr[dg];
            *(float4*)&sKV[j * 64 + dg + 4] = *(const float4*)&vr[dg + 4];
        }
        __syncthreads();

#pragma unroll 4
        for (int jj = 0; jj < 32; jj++) {
            const float p0 = sS[(ty * 4 + 0) * SPAD + kt * 32 + jj];
            const float p1 = sS[(ty * 4 + 1) * SPAD + kt * 32 + jj];
            const float p2 = sS[(ty * 4 + 2) * SPAD + kt * 32 + jj];
            const float p3 = sS[(ty * 4 + 3) * SPAD + kt * 32 + jj];
            const float4 v = *(const float4*)&sKV[jj * 64 + tx * 4];
            oc[0][0] += p0 * v.x; oc[0][1] += p0 * v.y; oc[0][2] += p0 * v.z; oc[0][3] += p0 * v.w;
            oc[1][0] += p1 * v.x; oc[1][1] += p1 * v.y; oc[1][2] += p1 * v.z; oc[1][3] += p1 * v.w;
            oc[2][0] += p2 * v.x; oc[2][1] += p2 * v.y; oc[2][2] += p2 * v.z; oc[2][3] += p2 * v.w;
            oc[3][0] += p3 * v.x; oc[3][1] += p3 * v.y; oc[3][2] += p3 * v.z; oc[3][3] += p3 * v.w;
        }
    }

    {
        const size_t base = (tokBase + qt * 64 + ty * 4) * DM + h * HD + tx * 4;
#pragma unroll
        for (int i = 0; i < 4; i++) {
            *(float4*)&g_ao[base + (size_t)i * DM] =
                make_float4(oc[i][0], oc[i][1], oc[i][2], oc[i][3]);
        }
    }
}

// ===========================================================================
// Launch
// ===========================================================================
extern "C" void kernel_launch(void* const* d_in, const int* in_sizes, int n_in,
                              void* d_out, int out_size)
{
    (void)in_sizes; (void)n_in; (void)out_size;
    const float* x  = (const float*)d_in[0];
    const float* Wq = (const float*)d_in[1];
    const float* bq = (const float*)d_in[2];
    const float* Wk = (const float*)d_in[3];
    const float* bk = (const float*)d_in[4];
    const float* Wv = (const float*)d_in[5];
    const float* bv = (const float*)d_in[6];
    const float* Wo = (const float*)d_in[7];
    const float* bo = (const float*)d_in[8];
    float* out = (float*)d_out;

    float *p_lm, *p_klm, *p_vlm, *p_q, *p_kx, *p_vx, *p_ao;
    cudaGetSymbolAddress((void**)&p_lm,  g_lm);
    cudaGetSymbolAddress((void**)&p_klm, g_klm);
    cudaGetSymbolAddress((void**)&p_vlm, g_vlm);
    cudaGetSymbolAddress((void**)&p_q,   g_q);
    cudaGetSymbolAddress((void**)&p_kx,  g_kx);
    cudaGetSymbolAddress((void**)&p_vx,  g_vx);
    cudaGetSymbolAddress((void**)&p_ao,  g_ao);

    const int attn_smem = ATTN_SMEM_FLOATS * (int)sizeof(float);
    cudaFuncSetAttribute(attn_kernel,
                         cudaFuncAttributeMaxDynamicSharedMemorySize, attn_smem);

    // 1) landmarks
    lm_kernel<<<NB * NLM, 256>>>(x);

    // 2) projections (tensor cores via mma.sync, split-bf16)
    const dim3 gproj(DM / 128, (NB * SQL) / 128);   // 6 x 128
    mma_gemm<<<gproj, 256>>>(x, Wq, bq, p_q);
    mma_gemm<<<gproj, 256>>>(x, Wk, bk, p_kx);
    mma_gemm<<<gproj, 256>>>(x, Wv, bv, p_vx);
    const dim3 glm(DM / 128, 1);
    sgemm_abt<<<glm, 256>>>(p_lm, Wk, bk, p_klm, NB * NLM, DM, DM);
    sgemm_abt<<<glm, 256>>>(p_lm, Wv, bv, p_vlm, NB * NLM, DM, DM);

    // 3) fused chunked attention
    attn_kernel<<<dim3(CK / 64, NH, NB * NCH), 256, attn_smem>>>();

    // 4) output projection (tensor cores)
    mma_gemm<<<gproj, 256>>>(p_ao, Wo, bo, out);
}

// round 7
// speedup vs baseline: 1.7834x; 1.3352x over previous
#include <cuda_runtime.h>
#include <cuda_bf16.h>
#include <cstdint>

// ---------------------------------------------------------------------------
// ChunkedLocalAttention: mma.sync split-bf16 GEMMs + mma.sync attention
// B=2, S=8192, D=768, H=12, hd=64, CHUNK=512, N_LM=32
// Harness target is plain sm_100 -> stable-ISA ldmatrix + mma.sync only.
// ---------------------------------------------------------------------------

#define NB   2
#define SQL  8192
#define DM   768
#define NH   12
#define HD   64
#define CK   512
#define NLM  32
#define NCH  16
#define KVL  544
#define SEG  256
#define SPAD 548     // fp32 score row stride

// ---- device scratch -------------------------------------------------------
__device__ float g_lm [NB*NLM*DM];
__device__ float g_klm[NB*NLM*DM];
__device__ float g_vlm[NB*NLM*DM];
__device__ float g_q  [NB*SQL*DM];
__device__ float g_kx [NB*SQL*DM];
__device__ float g_vx [NB*SQL*DM];
__device__ float g_ao [NB*SQL*DM];

// ===========================================================================
// warp-mma helpers (stable ISA: sm_80+)
// ===========================================================================
__device__ __forceinline__ uint32_t smem_u32(const void* p) {
    return (uint32_t)__cvta_generic_to_shared(p);
}
__device__ __forceinline__ void ldsm_x4(uint32_t addr, uint32_t* r) {
    asm volatile("ldmatrix.sync.aligned.m8n8.x4.shared.b16 {%0,%1,%2,%3}, [%4];"
                 : "=r"(r[0]), "=r"(r[1]), "=r"(r[2]), "=r"(r[3]) : "r"(addr));
}
__device__ __forceinline__ void ldsm_x2(uint32_t addr, uint32_t* r) {
    asm volatile("ldmatrix.sync.aligned.m8n8.x2.shared.b16 {%0,%1}, [%2];"
                 : "=r"(r[0]), "=r"(r[1]) : "r"(addr));
}
__device__ __forceinline__ void ldsm_x2t(uint32_t addr, uint32_t* r) {
    asm volatile("ldmatrix.sync.aligned.m8n8.x2.trans.shared.b16 {%0,%1}, [%2];"
                 : "=r"(r[0]), "=r"(r[1]) : "r"(addr));
}
__device__ __forceinline__ void mma16816(float* c, const uint32_t* a, const uint32_t* b) {
    asm volatile("mma.sync.aligned.m16n8k16.row.col.f32.bf16.bf16.f32 "
                 "{%0,%1,%2,%3}, {%4,%5,%6,%7}, {%8,%9}, {%0,%1,%2,%3};"
                 : "+f"(c[0]), "+f"(c[1]), "+f"(c[2]), "+f"(c[3])
                 : "r"(a[0]), "r"(a[1]), "r"(a[2]), "r"(a[3]), "r"(b[0]), "r"(b[1]));
}

// split 8 fp32 -> hi/lo bf16 packs ;  x = hi + lo with |lo| <= 2^-9 |x|
__device__ __forceinline__ void cvt8(float4 a, float4 b, uint4& hi, uint4& lo) {
    float v[8] = {a.x, a.y, a.z, a.w, b.x, b.y, b.z, b.w};
    uint32_t h[8], l[8];
#pragma unroll
    for (int i = 0; i < 8; i++) {
        __nv_bfloat16 bh = __float2bfloat16(v[i]);
        __nv_bfloat16 bl = __float2bfloat16(v[i] - __bfloat162float(bh));
        h[i] = (uint32_t)__bfloat16_as_ushort(bh);
        l[i] = (uint32_t)__bfloat16_as_ushort(bl);
    }
    hi = make_uint4(h[0] | (h[1] << 16), h[2] | (h[3] << 16),
                    h[4] | (h[5] << 16), h[6] | (h[7] << 16));
    lo = make_uint4(l[0] | (l[1] << 16), l[2] | (l[3] << 16),
                    l[4] | (l[5] << 16), l[6] | (l[7] << 16));
}

// ===========================================================================
// mma.sync GEMM core: C = A[M,768] * W[768,768]^T + bias
// CTA 128x128, BK=32, 8 warps (2M x 4N), split-bf16 3-pass
// ===========================================================================
#define LDSR 40

__device__ __forceinline__ void gemm_body(
    const float* __restrict__ A, const float* __restrict__ W,
    const float* __restrict__ bias, float* __restrict__ C,
    int rowBlk, int colBlk)
{
    __shared__ __align__(16) __nv_bfloat16 sAh[128 * LDSR];
    __shared__ __align__(16) __nv_bfloat16 sAl[128 * LDSR];
    __shared__ __align__(16) __nv_bfloat16 sBh[128 * LDSR];
    __shared__ __align__(16) __nv_bfloat16 sBl[128 * LDSR];
    __shared__ float sBias[128];

    const int tid  = threadIdx.x;
    const int wid  = tid >> 5;
    const int lane = tid & 31;
    const int wm   = wid & 1;
    const int wn   = wid >> 1;

    if (tid < 128) sBias[tid] = bias[colBlk + tid];

    const int ldRow = tid >> 1;
    const int ldSeg = (tid & 1) * 16;
    const float* gA = A + (size_t)(rowBlk + ldRow) * DM + ldSeg;
    const float* gB = W + (size_t)(colBlk + ldRow) * DM + ldSeg;

    const uint32_t aOffB = (uint32_t)(((wm * 64 + (lane & 15)) * LDSR + ((lane >> 4) & 1) * 8) * 2);
    const uint32_t bOffB = (uint32_t)(((wn * 32 + (lane & 7))  * LDSR + ((lane >> 3) & 1) * 8) * 2);
    const uint32_t bAh = smem_u32(sAh) + aOffB;
    const uint32_t bAl = smem_u32(sAl) + aOffB;
    const uint32_t bBh = smem_u32(sBh) + bOffB;
    const uint32_t bBl = smem_u32(sBl) + bOffB;

    float acc[4][4][4];
#pragma unroll
    for (int i = 0; i < 4; i++)
#pragma unroll
        for (int j = 0; j < 4; j++)
#pragma unroll
            for (int k = 0; k < 4; k++) acc[i][j][k] = 0.f;

    float4 pa[4], pb[4];
#pragma unroll
    for (int i = 0; i < 4; i++) {
        pa[i] = *(const float4*)(gA + i * 4);
        pb[i] = *(const float4*)(gB + i * 4);
    }

    for (int t = 0; t < DM / 32; t++) {
        {
            uint4 hi, lo;
            const int so = ldRow * LDSR + ldSeg;
            cvt8(pa[0], pa[1], hi, lo);
            *(uint4*)&sAh[so] = hi;      *(uint4*)&sAl[so] = lo;
            cvt8(pa[2], pa[3], hi, lo);
            *(uint4*)&sAh[so + 8] = hi;  *(uint4*)&sAl[so + 8] = lo;
            cvt8(pb[0], pb[1], hi, lo);
            *(uint4*)&sBh[so] = hi;      *(uint4*)&sBl[so] = lo;
            cvt8(pb[2], pb[3], hi, lo);
            *(uint4*)&sBh[so + 8] = hi;  *(uint4*)&sBl[so + 8] = lo;
        }
        __syncthreads();

        if (t + 1 < DM / 32) {
            const int kn = (t + 1) * 32;
#pragma unroll
            for (int i = 0; i < 4; i++) {
                pa[i] = *(const float4*)(gA + kn + i * 4);
                pb[i] = *(const float4*)(gB + kn + i * 4);
            }
        }

#pragma unroll
        for (int ks = 0; ks < 2; ks++) {
            uint32_t ah[4][4], al[4][4], bh[4][2], bl[4][2];
#pragma unroll
            for (int mf = 0; mf < 4; mf++) {
                ldsm_x4(bAh + mf * (16 * LDSR * 2) + ks * 32, ah[mf]);
                ldsm_x4(bAl + mf * (16 * LDSR * 2) + ks * 32, al[mf]);
            }
#pragma unroll
            for (int nf = 0; nf < 4; nf++) {
                ldsm_x2(bBh + nf * (8 * LDSR * 2) + ks * 32, bh[nf]);
                ldsm_x2(bBl + nf * (8 * LDSR * 2) + ks * 32, bl[nf]);
            }
#pragma unroll
            for (int mf = 0; mf < 4; mf++)
#pragma unroll
                for (int nf = 0; nf < 4; nf++) {
                    mma16816(acc[mf][nf], ah[mf], bh[nf]);
                    mma16816(acc[mf][nf], ah[mf], bl[nf]);
                    mma16816(acc[mf][nf], al[mf], bh[nf]);
                }
        }
        __syncthreads();
    }

    const int mrow  = rowBlk + wm * 64 + (lane >> 2);
    const int cloc0 = wn * 32 + (lane & 3) * 2;
#pragma unroll
    for (int mf = 0; mf < 4; mf++) {
#pragma unroll
        for (int nf = 0; nf < 4; nf++) {
            const int cl = cloc0 + nf * 8;
            const int gc = colBlk + cl;
            float* c0 = C + (size_t)(mrow + mf * 16) * DM + gc;
            float* c1 = C + (size_t)(mrow + mf * 16 + 8) * DM + gc;
            *(float2*)c0 = make_float2(acc[mf][nf][0] + sBias[cl],
                                       acc[mf][nf][1] + sBias[cl + 1]);
            *(float2*)c1 = make_float2(acc[mf][nf][2] + sBias[cl],
                                       acc[mf][nf][3] + sBias[cl + 1]);
        }
    }
}

__global__ __launch_bounds__(256, 1) void mma_gemm(
    const float* __restrict__ A, const float* __restrict__ W,
    const float* __restrict__ bias, float* __restrict__ C)
{
    gemm_body(A, W, bias, C, blockIdx.y * 128, blockIdx.x * 128);
}

__global__ __launch_bounds__(256, 1) void mma_gemm3(
    const float* __restrict__ A,
    const float* __restrict__ W0, const float* __restrict__ b0, float* __restrict__ C0,
    const float* __restrict__ W1, const float* __restrict__ b1, float* __restrict__ C1,
    const float* __restrict__ W2, const float* __restrict__ b2, float* __restrict__ C2)
{
    const int z = blockIdx.z;
    const float* W = (z == 0) ? W0 : (z == 1) ? W1 : W2;
    const float* b = (z == 0) ? b0 : (z == 1) ? b1 : b2;
    float*       C = (z == 0) ? C0 : (z == 1) ? C1 : C2;
    gemm_body(A, W, b, C, blockIdx.y * 128, blockIdx.x * 128);
}

// ===========================================================================
// Landmark mean-pool
// ===========================================================================
__global__ __launch_bounds__(256) void lm_kernel(const float* __restrict__ x)
{
    const int b = blockIdx.x / NLM;
    const int l = blockIdx.x % NLM;
    const float* xp = x + ((size_t)(b * SQL) + (size_t)l * SEG) * DM;
    const int t = threadIdx.x;
    float a0 = 0.f, a1 = 0.f, a2 = 0.f;
    for (int s = 0; s < SEG; s++) {
        const float* r = xp + (size_t)s * DM;
        a0 += r[t]; a1 += r[t + 256]; a2 += r[t + 512];
    }
    float* o = g_lm + (size_t)(b * NLM + l) * DM;
    const float inv = 1.0f / (float)SEG;
    o[t] = a0 * inv; o[t + 256] = a1 * inv; o[t + 512] = a2 * inv;
}

// ===========================================================================
// small SIMT SGEMM for landmark K/V projections (M=64), z selects K vs V
// ===========================================================================
__global__ __launch_bounds__(256, 2) void sgemm_lm(
    const float* __restrict__ A,
    const float* __restrict__ Wk, const float* __restrict__ bk, float* __restrict__ Ck,
    const float* __restrict__ Wv, const float* __restrict__ bv, float* __restrict__ Cv)
{
    const float* W    = blockIdx.z ? Wv : Wk;
    const float* bias = blockIdx.z ? bv : bk;
    float*       C    = blockIdx.z ? Cv : Ck;
    const int M = NB * NLM, N = DM, K = DM;

    __shared__ float As[16][132];
    __shared__ float Bs[16][132];
    const int tid = threadIdx.x;
    const int tx  = tid & 15;
    const int ty  = tid >> 4;
    const int colBlk = blockIdx.x * 128;
    const int lr = tid >> 2;
    const int lk = (tid & 3) << 2;

    float acc[8][8];
#pragma unroll
    for (int i = 0; i < 8; i++)
#pragma unroll
        for (int j = 0; j < 8; j++) acc[i][j] = 0.f;

    for (int kt = 0; kt < K; kt += 16) {
#pragma unroll
        for (int rr = 0; rr < 2; rr++) {
            const int r = lr + rr * 64;
            float4 va = make_float4(0.f, 0.f, 0.f, 0.f);
            if (r < M) va = *(const float4*)&A[(size_t)r * K + kt + lk];
            As[lk + 0][r] = va.x; As[lk + 1][r] = va.y;
            As[lk + 2][r] = va.z; As[lk + 3][r] = va.w;
            const float4 vb = *(const float4*)&W[(size_t)(colBlk + r) * K + kt + lk];
            Bs[lk + 0][r] = vb.x; Bs[lk + 1][r] = vb.y;
            Bs[lk + 2][r] = vb.z; Bs[lk + 3][r] = vb.w;
        }
        __syncthreads();
#pragma unroll
        for (int kk = 0; kk < 16; kk++) {
            float a[8], bb[8];
            *(float4*)&a[0]  = *(const float4*)&As[kk][ty * 8];
            *(float4*)&a[4]  = *(const float4*)&As[kk][ty * 8 + 4];
            *(float4*)&bb[0] = *(const float4*)&Bs[kk][tx * 8];
            *(float4*)&bb[4] = *(const float4*)&Bs[kk][tx * 8 + 4];
#pragma unroll
            for (int i = 0; i < 8; i++)
#pragma unroll
                for (int j = 0; j < 8; j++) acc[i][j] += a[i] * bb[j];
        }
        __syncthreads();
    }
#pragma unroll
    for (int i = 0; i < 8; i++) {
        const int gr = ty * 8 + i;
        if (gr < M) {
#pragma unroll
            for (int j = 0; j < 8; j += 4) {
                const int gc = colBlk + tx * 8 + j;
                float4 v;
                v.x = acc[i][j + 0] + bias[gc + 0];
                v.y = acc[i][j + 1] + bias[gc + 1];
                v.z = acc[i][j + 2] + bias[gc + 2];
                v.w = acc[i][j + 3] + bias[gc + 3];
                *(float4*)&C[(size_t)gr * N + gc] = v;
            }
        }
    }
}

// ===========================================================================
// Fused attention via mma.sync, split-bf16 both GEMMs.
// Block = (64 q rows, head, b*chunk). 8 warps: wm = wid&1 (32 rows),
// wn = wid>>1 (N groups). kv processed in 17 tiles of 32 (tile 0 = landmarks).
// ===========================================================================
#define QSTR 72          // bf16 row stride for Q/K/V staging (144B)
#define PSTR 40          // bf16 row stride for P staging (80B)
#define S_BYTES   (64 * SPAD * 4)
#define OFF_QH    S_BYTES
#define OFF_QL    (OFF_QH + 64 * QSTR * 2)
#define OFF_KH    (OFF_QL + 64 * QSTR * 2)
#define OFF_KL    (OFF_KH + 32 * QSTR * 2)
#define ATTN_SMEM (OFF_KL + 32 * QSTR * 2)   // 167,936 B

__global__ __launch_bounds__(256) void attn_mma()
{
    extern __shared__ char sm[];
    float* sS = (float*)sm;
    __nv_bfloat16* sQh = (__nv_bfloat16*)(sm + OFF_QH);
    __nv_bfloat16* sQl = (__nv_bfloat16*)(sm + OFF_QL);
    __nv_bfloat16* sKh = (__nv_bfloat16*)(sm + OFF_KH);
    __nv_bfloat16* sKl = (__nv_bfloat16*)(sm + OFF_KL);
    __nv_bfloat16* sPh = sQh;   // phase-3 aliases (Q dead after frag hoist)
    __nv_bfloat16* sPl = sQl;
    __nv_bfloat16* sVh = sKh;
    __nv_bfloat16* sVl = sKl;

    const int tid  = threadIdx.x;
    const int wid  = tid >> 5;
    const int lane = tid & 31;
    const int wm   = wid & 1;
    const int wn   = wid >> 1;
    const int qt   = blockIdx.x;
    const int h    = blockIdx.y;
    const int bc   = blockIdx.z;
    const int b    = bc >> 4;
    const int c    = bc & 15;
    const float scale = 0.125f;
    const size_t tokBase = (size_t)(b * SQL + c * CK);

    // ---- stage Q (64 x 64) split hi/lo ----
    {
        const int row = tid >> 2, dseg = (tid & 3) * 16;
        const float* qr = g_q + (tokBase + qt * 64 + row) * DM + h * HD + dseg;
        uint4 hi, lo;
        cvt8(*(const float4*)qr, *(const float4*)(qr + 4), hi, lo);
        *(uint4*)&sQh[row * QSTR + dseg] = hi;
        *(uint4*)&sQl[row * QSTR + dseg] = lo;
        cvt8(*(const float4*)(qr + 8), *(const float4*)(qr + 12), hi, lo);
        *(uint4*)&sQh[row * QSTR + dseg + 8] = hi;
        *(uint4*)&sQl[row * QSTR + dseg + 8] = lo;
    }
    __syncthreads();

    // ---- hoist Q fragments: 2 m-frags x 4 k-segs, hi+lo ----
    uint32_t qh[2][4][4], ql[2][4][4];
    {
        const uint32_t qb  = smem_u32(sQh);
        const uint32_t qlb = smem_u32(sQl);
        const uint32_t lrow = (uint32_t)(lane & 15);
        const uint32_t lk8  = (uint32_t)(((lane >> 4) & 1) * 8);
#pragma unroll
        for (int mf = 0; mf < 2; mf++)
#pragma unroll
            for (int ks = 0; ks < 4; ks++) {
                const uint32_t off = ((wm * 32 + mf * 16 + lrow) * QSTR + ks * 16 + lk8) * 2;
                ldsm_x4(qb + off, qh[mf][ks]);
                ldsm_x4(qlb + off, ql[mf][ks]);
            }
    }

    // ---- Phase 1: S = scale * Q K^T, 17 kv tiles of 32 ----
    for (int kt = 0; kt < 17; kt++) {
        if (kt) __syncthreads();
        {
            const int j = tid >> 3, dseg = (tid & 7) * 8;
            const float* kr = (kt == 0)
                ? g_klm + ((size_t)(b * NLM + j)) * DM + h * HD + dseg
                : g_kx  + (tokBase + (kt - 1) * 32 + j) * DM + h * HD + dseg;
            uint4 hi, lo;
            cvt8(*(const float4*)kr, *(const float4*)(kr + 4), hi, lo);
            *(uint4*)&sKh[j * QSTR + dseg] = hi;
            *(uint4*)&sKl[j * QSTR + dseg] = lo;
        }
        __syncthreads();

        float acc[2][4] = {{0.f,0.f,0.f,0.f},{0.f,0.f,0.f,0.f}};
        const uint32_t kb   = smem_u32(sKh);
        const uint32_t klb  = smem_u32(sKl);
        const uint32_t nrow = (uint32_t)(wn * 8 + (lane & 7));
        const uint32_t lk8  = (uint32_t)(((lane >> 3) & 1) * 8);
#pragma unroll
        for (int ks = 0; ks < 4; ks++) {
            uint32_t kh[2], kl[2];
            const uint32_t off = (nrow * QSTR + ks * 16 + lk8) * 2;
            ldsm_x2(kb + off, kh);
            ldsm_x2(klb + off, kl);
#pragma unroll
            for (int mf = 0; mf < 2; mf++) {
                mma16816(acc[mf], qh[mf][ks], kh);
                mma16816(acc[mf], qh[mf][ks], kl);
                mma16816(acc[mf], ql[mf][ks], kh);
            }
        }
        const int col = kt * 32 + wn * 8 + (lane & 3) * 2;
#pragma unroll
        for (int mf = 0; mf < 2; mf++) {
            const int r0 = wm * 32 + mf * 16 + (lane >> 2);
            sS[r0 * SPAD + col]           = acc[mf][0] * scale;
            sS[r0 * SPAD + col + 1]       = acc[mf][1] * scale;
            sS[(r0 + 8) * SPAD + col]     = acc[mf][2] * scale;
            sS[(r0 + 8) * SPAD + col + 1] = acc[mf][3] * scale;
        }
    }
    __syncthreads();

    // ---- Phase 2: softmax (8 warps x 8 rows) ----
    for (int rr = 0; rr < 8; rr++) {
        float* row = sS + (size_t)(wid * 8 + rr) * SPAD;
        float m = -1e30f;
        for (int j = lane; j < KVL; j += 32) m = fmaxf(m, row[j]);
#pragma unroll
        for (int o = 16; o > 0; o >>= 1) m = fmaxf(m, __shfl_xor_sync(0xffffffffu, m, o));
        float ssum = 0.f;
        for (int j = lane; j < KVL; j += 32) {
            const float e = __expf(row[j] - m);
            row[j] = e;
            ssum += e;
        }
#pragma unroll
        for (int o = 16; o > 0; o >>= 1) ssum += __shfl_xor_sync(0xffffffffu, ssum, o);
        const float inv = 1.0f / ssum;
        for (int j = lane; j < KVL; j += 32) row[j] *= inv;
    }

    // ---- Phase 3: O = P V, warp tile 32 x 16 (2 m-frags x 2 n-frags) ----
    float oacc[2][2][4];
#pragma unroll
    for (int i = 0; i < 2; i++)
#pragma unroll
        for (int j = 0; j < 2; j++)
#pragma unroll
            for (int k = 0; k < 4; k++) oacc[i][j][k] = 0.f;

    for (int kt = 0; kt < 17; kt++) {
        __syncthreads();
        {   // stage P tile [64 x 32] from S (fp32 -> split bf16)
            const int row = tid >> 2, cseg = (tid & 3) * 8;
            const float* sp = sS + (size_t)row * SPAD + kt * 32 + cseg;
            uint4 hi, lo;
            cvt8(*(const float4*)sp, *(const float4*)(sp + 4), hi, lo);
            *(uint4*)&sPh[row * PSTR + cseg] = hi;
            *(uint4*)&sPl[row * PSTR + cseg] = lo;
        }
        {   // stage V tile [32 x 64]
            const int j = tid >> 3, dseg = (tid & 7) * 8;
            const float* vr = (kt == 0)
                ? g_vlm + ((size_t)(b * NLM + j)) * DM + h * HD + dseg
                : g_vx  + (tokBase + (kt - 1) * 32 + j) * DM + h * HD + dseg;
            uint4 hi, lo;
            cvt8(*(const float4*)vr, *(const float4*)(vr + 4), hi, lo);
            *(uint4*)&sVh[j * QSTR + dseg] = hi;
            *(uint4*)&sVl[j * QSTR + dseg] = lo;
        }
        __syncthreads();

        const uint32_t pb  = smem_u32(sPh);
        const uint32_t plb = smem_u32(sPl);
        const uint32_t vb  = smem_u32(sVh);
        const uint32_t vlb = smem_u32(sVl);
#pragma unroll
        for (int ks = 0; ks < 2; ks++) {
            uint32_t ph[2][4], pl[2][4];
#pragma unroll
            for (int mf = 0; mf < 2; mf++) {
                const uint32_t off =
                    ((wm * 32 + mf * 16 + (lane & 15)) * PSTR + ks * 16 + ((lane >> 4) & 1) * 8) * 2;
                ldsm_x4(pb + off, ph[mf]);
                ldsm_x4(plb + off, pl[mf]);
            }
            uint32_t vh[2][2], vl[2][2];
#pragma unroll
            for (int nf = 0; nf < 2; nf++) {
                const uint32_t off =
                    ((ks * 16 + (lane & 7) + ((lane >> 3) & 1) * 8) * QSTR + wn * 16 + nf * 8) * 2;
                ldsm_x2t(vb + off, vh[nf]);
                ldsm_x2t(vlb + off, vl[nf]);
            }
#pragma unroll
            for (int mf = 0; mf < 2; mf++)
#pragma unroll
                for (int nf = 0; nf < 2; nf++) {
                    mma16816(oacc[mf][nf], ph[mf], vh[nf]);
                    mma16816(oacc[mf][nf], ph[mf], vl[nf]);
                    mma16816(oacc[mf][nf], pl[mf], vh[nf]);
                }
        }
    }

    // ---- store O ----
    const int orow0 = wm * 32 + (lane >> 2);
    const int ocol  = wn * 16 + (lane & 3) * 2;
#pragma unroll
    for (int mf = 0; mf < 2; mf++) {
#pragma unroll
        for (int nf = 0; nf < 2; nf++) {
            const int col = ocol + nf * 8;
            float* o0 = g_ao + (tokBase + qt * 64 + orow0 + mf * 16) * DM + h * HD + col;
            float* o1 = g_ao + (tokBase + qt * 64 + orow0 + mf * 16 + 8) * DM + h * HD + col;
            *(float2*)o0 = make_float2(oacc[mf][nf][0], oacc[mf][nf][1]);
            *(float2*)o1 = make_float2(oacc[mf][nf][2], oacc[mf][nf][3]);
        }
    }
}

// ===========================================================================
// Launch
// ===========================================================================
extern "C" void kernel_launch(void* const* d_in, const int* in_sizes, int n_in,
                              void* d_out, int out_size)
{
    (void)in_sizes; (void)n_in; (void)out_size;
    const float* x  = (const float*)d_in[0];
    const float* Wq = (const float*)d_in[1];
    const float* bq = (const float*)d_in[2];
    const float* Wk = (const float*)d_in[3];
    const float* bk = (const float*)d_in[4];
    const float* Wv = (const float*)d_in[5];
    const float* bv = (const float*)d_in[6];
    const float* Wo = (const float*)d_in[7];
    const float* bo = (const float*)d_in[8];
    float* out = (float*)d_out;

    float *p_lm, *p_klm, *p_vlm, *p_q, *p_kx, *p_vx, *p_ao;
    cudaGetSymbolAddress((void**)&p_lm,  g_lm);
    cudaGetSymbolAddress((void**)&p_klm, g_klm);
    cudaGetSymbolAddress((void**)&p_vlm, g_vlm);
    cudaGetSymbolAddress((void**)&p_q,   g_q);
    cudaGetSymbolAddress((void**)&p_kx,  g_kx);
    cudaGetSymbolAddress((void**)&p_vx,  g_vx);
    cudaGetSymbolAddress((void**)&p_ao,  g_ao);

    cudaFuncSetAttribute(attn_mma,
                         cudaFuncAttributeMaxDynamicSharedMemorySize, ATTN_SMEM);

    // 1) landmarks
    lm_kernel<<<NB * NLM, 256>>>(x);

    // 2) fused QKV projections + landmark K/V
    mma_gemm3<<<dim3(DM / 128, (NB * SQL) / 128, 3), 256>>>(
        x, Wq, bq, p_q, Wk, bk, p_kx, Wv, bv, p_vx);
    sgemm_lm<<<dim3(DM / 128, 1, 2), 256>>>(p_lm, Wk, bk, p_klm, Wv, bv, p_vlm);

    // 3) fused chunked attention (tensor cores)
    attn_mma<<<dim3(CK / 64, NH, NB * NCH), 256, ATTN_SMEM>>>();

    // 4) output projection
    mma_gemm<<<dim3(DM / 128, (NB * SQL) / 128), 256>>>(p_ao, Wo, bo, out);
}